// round 16
// baseline (speedup 1.0000x reference)
#include <cuda_runtime.h>
#include <cuda_fp16.h>
#include <mma.h>
#include <math.h>
#include <cstdint>

using namespace nvcuda;
typedef __half hf;

#define Bb 2
#define Nn 2048
#define MM_ 2048
#define Dd 1024
#define Hh 8
#define DHd 64
#define INNERi 512
#define FFDf 4096

#define BND  (Bb*Nn*Dd)
#define BNI  (Bb*Nn*INNERi)
#define BNF  (Bb*Nn*FFDf)
#define DW   (Dd*INNERi)
#define DF   ((long)Dd*FFDf)

// ---------------- scratch ----------------------------------------------------
__device__ __align__(256) float g_x1c [2*BND];
__device__ __align__(256) float g_resin[2*BND];
__device__ __align__(256) float g_bo[2*Dd];
__device__ __align__(256) float g_b1[2*FFDf];
__device__ __align__(256) float g_b2[2*Dd];
__device__ __align__(256) hf g_simb [Bb*Hh*Nn*MM_];
__device__ __align__(256) hf g_attn [Bb*Hh*Nn*MM_];
__device__ __align__(256) hf g_cattn[Bb*Hh*Nn*MM_];
__device__ __align__(256) hf g_qkv[4*BNI];
__device__ __align__(256) hf g_oc [2*BNI];
__device__ __align__(256) hf g_xc [2*BND];
__device__ __align__(256) hf g_hb [2*BNF];
__device__ __align__(256) hf g_wp [4*DW];
__device__ __align__(256) hf g_wo [2*DW];
__device__ __align__(256) hf g_f1 [2*DF];
__device__ __align__(256) hf g_f2 [2*DF];
__device__ int g_mask_mode;

// ---------------- merged f32 -> fp16 weight convert (10 segments) --------------
__global__ __launch_bounds__(256)
void convall(const float4* s0, const float4* s1, const float4* s2, const float4* s3,
             const float4* s4, const float4* s5, const float4* s6, const float4* s7,
             const float4* s8, const float4* s9,
             __half2* d0, __half2* d1, __half2* d2, __half2* d3, __half2* d4,
             __half2* d5, __half2* d6, __half2* d7, __half2* d8, __half2* d9)
{
    int seg = blockIdx.y;
    const float4* in; __half2* out; int n4;
    switch (seg) {
        case 0: in = s0; out = d0; n4 = DW / 4; break;
        case 1: in = s1; out = d1; n4 = DW / 4; break;
        case 2: in = s2; out = d2; n4 = DW / 4; break;
        case 3: in = s3; out = d3; n4 = DW / 4; break;
        case 4: in = s4; out = d4; n4 = DW / 4; break;
        case 5: in = s5; out = d5; n4 = DW / 4; break;
        case 6: in = s6; out = d6; n4 = (int)(DF / 4); break;
        case 7: in = s7; out = d7; n4 = (int)(DF / 4); break;
        case 8: in = s8; out = d8; n4 = (int)(DF / 4); break;
        default: in = s9; out = d9; n4 = (int)(DF / 4); break;
    }
    for (int i = blockIdx.x * 256 + threadIdx.x; i < n4; i += gridDim.x * 256) {
        float4 v = in[i];
        out[2 * i]     = __floats2half2_rn(v.x, v.y);
        out[2 * i + 1] = __floats2half2_rn(v.z, v.w);
    }
}

// ---------------- mask detection ---------------------------------------------
__global__ void detect_mask_mode(const float* __restrict__ fp, int n4)
{
    __shared__ int okf_s, oki_s;
    if (threadIdx.x == 0) { okf_s = 1; oki_s = 1; }
    __syncthreads();
    const int* ip = (const int*)fp;
    bool okf = true, oki = true;
    for (int i = threadIdx.x; i < n4; i += 256) {
        float fv = fp[i]; okf = okf && (fv == 0.f || fv == 1.f);
        int   iv = ip[i]; oki = oki && (iv == 0 || iv == 1);
    }
    if (!okf) atomicAnd(&okf_s, 0);
    if (!oki) atomicAnd(&oki_s, 0);
    __syncthreads();
    if (threadIdx.x == 0) g_mask_mode = okf_s ? 2 : (oki_s ? 1 : 0);
}
__device__ __forceinline__ bool mask_at(const void* m, int i, int mode)
{
    if (mode == 1) return ((const int*)m)[i] != 0;
    if (mode == 2) return ((const float*)m)[i] != 0.f;
    return ((const unsigned char*)m)[i] != 0;
}

// ---------------- dual-side LayerNorm -> fp16 ----------------------------------
__global__ __launch_bounds__(256)
void ln2(const float* __restrict__ inA, const float* __restrict__ inB, int RA,
         const float* __restrict__ gA, const float* __restrict__ bA,
         const float* __restrict__ gB, const float* __restrict__ bB,
         hf* __restrict__ oh, int cols)
{
    __shared__ float r1[256], r2[256];
    long row = blockIdx.x;
    bool sec = row >= RA;
    const float* p = sec ? inB + (row - RA) * cols : inA + row * cols;
    const float* g = sec ? gB : gA;
    const float* b = sec ? bB : bA;
    hf* ph = oh + row * cols;
    int tid = threadIdx.x;
    float s = 0.f, s2 = 0.f;
    for (int c = tid; c < cols; c += 256) { float v = p[c]; s += v; s2 += v * v; }
    r1[tid] = s; r2[tid] = s2; __syncthreads();
    for (int st = 128; st > 0; st >>= 1) {
        if (tid < st) { r1[tid] += r1[tid + st]; r2[tid] += r2[tid + st]; }
        __syncthreads();
    }
    float mu  = r1[0] / cols;
    float var = r2[0] / cols - mu * mu;
    float inv = rsqrtf(var + 1e-5f);
    for (int c = tid; c < cols; c += 256)
        ph[c] = __float2half((p[c] - mu) * inv * g[c] + b[c]);
}

// ---------------- fused dual softmax (row blocks then col blocks) --------------
#define ROWBLK (Bb*Hh*Nn)            // 32768
#define COLBLK ((MM_/32)*(Bb*Hh))    // 1024
__global__ __launch_bounds__(256)
void softmax_both(const hf* __restrict__ sim, hf* __restrict__ attn,
                  hf* __restrict__ cattn,
                  const void* __restrict__ mask, const void* __restrict__ cmask)
{
    __shared__ float buf[MM_];
    __shared__ float red[256];
    int mode = g_mask_mode;
    if (blockIdx.x < ROWBLK) {
        long row = blockIdx.x;
        int i = (int)(row % Nn), bh = (int)(row / Nn), b = bh / Hh;
        const hf* src = sim  + row * (long)MM_;
        hf*       dst = attn + row * (long)MM_;
        int tid = threadIdx.x;
        bool mi = mask_at(mask, b * Nn + i, mode);
        float lmax = -3.402823466e38f;
        for (int j = tid; j < MM_; j += 256) {
            bool mj = mask_at(cmask, b * MM_ + j, mode);
            float vv = (mi && mj) ? __half2float(src[j]) : -3.402823466e38f;
            buf[j] = vv; lmax = fmaxf(lmax, vv);
        }
        red[tid] = lmax; __syncthreads();
        for (int s = 128; s > 0; s >>= 1) {
            if (tid < s) red[tid] = fmaxf(red[tid], red[tid + s]);
            __syncthreads();
        }
        float rmax = red[0]; __syncthreads();
        float lsum = 0.f;
        for (int j = tid; j < MM_; j += 256) { float e = expf(buf[j] - rmax); buf[j] = e; lsum += e; }
        red[tid] = lsum; __syncthreads();
        for (int s = 128; s > 0; s >>= 1) {
            if (tid < s) red[tid] += red[tid + s];
            __syncthreads();
        }
        float inv = 1.f / red[0];
        for (int j = tid; j < MM_; j += 256) dst[j] = __float2half(buf[j] * inv);
    } else {
        // col softmax: 32 cols x 8 row-groups per block
        float (*sm)[32] = (float(*)[32])buf;          // [8][32]
        float (*ss)[32] = (float(*)[32])(buf + 256);  // [8][32]
        int idx = blockIdx.x - ROWBLK;
        int jblk = idx % (MM_ / 32);
        int z    = idx / (MM_ / 32);
        int b = z / Hh;
        int c = threadIdx.x & 31, g = threadIdx.x >> 5;
        int j = jblk * 32 + c;
        const hf* base = sim   + (long)z * Nn * MM_;
        hf*       outb = cattn + (long)z * Nn * MM_;
        bool mj = mask_at(cmask, b * MM_ + j, mode);
        float m = -3.402823466e38f, s = 0.f;
        for (int i = g; i < Nn; i += 8) {
            bool mi = mask_at(mask, b * Nn + i, mode);
            float vv = (mj && mi) ? __half2float(base[(long)i * MM_ + j]) : -3.402823466e38f;
            if (vv > m) { s = s * expf(m - vv) + 1.f; m = vv; }
            else        { s += expf(vv - m); }
        }
        sm[g][c] = m; ss[g][c] = s; __syncthreads();
        if (g == 0) {
            float Ml = sm[0][c], Sl = ss[0][c];
            #pragma unroll
            for (int t = 1; t < 8; t++) {
                float mt = sm[t][c], st = ss[t][c];
                float nm = fmaxf(Ml, mt);
                Sl = Sl * expf(Ml - nm) + st * expf(mt - nm);
                Ml = nm;
            }
            sm[0][c] = Ml; ss[0][c] = 1.f / Sl;
        }
        __syncthreads();
        float Mg = sm[0][c], inv = ss[0][c];
        for (int i = g; i < Nn; i += 8) {
            bool mi = mask_at(mask, b * Nn + i, mode);
            float vv = (mj && mi) ? __half2float(base[(long)i * MM_ + j]) : -3.402823466e38f;
            outb[(long)i * MM_ + j] = __float2half(expf(vv - Mg) * inv);
        }
    }
}

// ---------------- fused PV (both directions, one launch) -----------------------
// z in [0,16): out  = attn[z]   @ cv[z]   (A row-major)
// z in [16,32): cout = cattn[z-16]^T @ v  (A col-major access)
__global__ __launch_bounds__(256)
void pv2(const hf* __restrict__ attn, const hf* __restrict__ cattn,
         const hf* __restrict__ v, const hf* __restrict__ cv,
         hf* __restrict__ oc)
{
    constexpr int BM = 128, BN = 64, BK = 64;
    constexpr int LDAR = BK + 8;                 // row-major A tile [BM][BK]
    constexpr int LDAT = BM + 8;                 // col-major A tile [BK][BM]
    constexpr int AEL  = BM * LDAR;              // 9216 >= BK*LDAT (8704)
    constexpr int LDBS = BN + 8;
    constexpr int BEL  = BK * LDBS;              // 4608
    constexpr int SEL  = AEL + BEL;
    constexpr int WRM = 4, WRN = 2, TM = 32, TN = 32, FM = 2, FN = 2;

    extern __shared__ hf smh_[];
    uint32_t sb0;
    asm("{ .reg .u64 t; cvta.to.shared.u64 t, %1; cvt.u32.u64 %0, t; }"
        : "=r"(sb0) : "l"(smh_));

    int z = blockIdx.z;
    bool tr = z >= 16;
    int zz = tr ? z - 16 : z;
    const hf* A  = (tr ? cattn : attn) + (long)zz * Nn * MM_;
    const hf* Bm = (tr ? v : cv) + (long)(zz / Hh) * Nn * INNERi + (zz % Hh) * DHd;
    hf* C = oc + (tr ? (long)BNI : 0L) + (long)(zz / Hh) * Nn * INNERi + (zz % Hh) * DHd;

    long m0 = (long)blockIdx.y * BM;
    int tid = threadIdx.x, warp = tid >> 5;
    int wm0 = (warp % WRM) * TM, wn0 = (warp / WRM) * TN;

    auto cpab = [](uint32_t s, const void* g) {
        asm volatile("cp.async.cg.shared.global [%0], [%1], 16;\n" :: "r"(s), "l"(g));
    };

    auto load_stage = [&](int s, int kt) {
        uint32_t base = sb0 + (uint32_t)(s * SEL * 2);
        int kb = kt * BK;
        if (!tr) {
            // A[m][k], 128 rows x 64 cols
            #pragma unroll
            for (int t = 0; t < 4; t++) {
                int idx = t * 256 + tid;
                int r = idx >> 3, c = (idx & 7);
                cpab(base + (uint32_t)((r * LDAR + c * 8) * 2),
                     A + (m0 + r) * (long)MM_ + kb + c * 8);
            }
        } else {
            // A[k][m] (cattn[i][j], k=i, m=j), 64 rows x 128 cols
            #pragma unroll
            for (int t = 0; t < 4; t++) {
                int idx = t * 256 + tid;
                int k = idx >> 4, mc = (idx & 15);
                cpab(base + (uint32_t)((k * LDAT + mc * 8) * 2),
                     A + (long)(kb + k) * MM_ + m0 + mc * 8);
            }
        }
        // B[k][n], 64 rows x 64 cols
        #pragma unroll
        for (int t = 0; t < 2; t++) {
            int idx = t * 256 + tid;
            int k = idx >> 3, c = (idx & 7);
            cpab(base + (uint32_t)((AEL + k * LDBS + c * 8) * 2),
                 Bm + (long)(kb + k) * INNERi + c * 8);
        }
        asm volatile("cp.async.commit_group;\n");
    };

    wmma::fragment<wmma::accumulator, 16, 16, 16, float> fc[FM][FN];
    #pragma unroll
    for (int i = 0; i < FM; i++)
        #pragma unroll
        for (int j = 0; j < FN; j++)
            wmma::fill_fragment(fc[i][j], 0.f);

    const int T = MM_ / BK;   // 32
    load_stage(0, 0);
    load_stage(1, 1);

    for (int kt = 0; kt < T; kt++) {
        if (kt + 1 < T) asm volatile("cp.async.wait_group 1;\n");
        else            asm volatile("cp.async.wait_group 0;\n");
        __syncthreads();
        if (kt + 2 < T) load_stage((kt + 2) % 3, kt + 2);

        const hf* st = smh_ + (kt % 3) * SEL;
        const hf* sA = st;
        const hf* sB = st + AEL;

        if (!tr) {
            #pragma unroll
            for (int kk = 0; kk < BK; kk += 16) {
                wmma::fragment<wmma::matrix_a, 16, 16, 16, hf, wmma::row_major> fa[FM];
                wmma::fragment<wmma::matrix_b, 16, 16, 16, hf, wmma::row_major> fb[FN];
                #pragma unroll
                for (int i = 0; i < FM; i++)
                    wmma::load_matrix_sync(fa[i], sA + (wm0 + i * 16) * LDAR + kk, LDAR);
                #pragma unroll
                for (int j = 0; j < FN; j++)
                    wmma::load_matrix_sync(fb[j], sB + kk * LDBS + wn0 + j * 16, LDBS);
                #pragma unroll
                for (int i = 0; i < FM; i++)
                    #pragma unroll
                    for (int j = 0; j < FN; j++)
                        wmma::mma_sync(fc[i][j], fa[i], fb[j], fc[i][j]);
            }
        } else {
            #pragma unroll
            for (int kk = 0; kk < BK; kk += 16) {
                wmma::fragment<wmma::matrix_a, 16, 16, 16, hf, wmma::col_major> fa[FM];
                wmma::fragment<wmma::matrix_b, 16, 16, 16, hf, wmma::row_major> fb[FN];
                #pragma unroll
                for (int i = 0; i < FM; i++)
                    wmma::load_matrix_sync(fa[i], sA + kk * LDAT + wm0 + i * 16, LDAT);
                #pragma unroll
                for (int j = 0; j < FN; j++)
                    wmma::load_matrix_sync(fb[j], sB + kk * LDBS + wn0 + j * 16, LDBS);
                #pragma unroll
                for (int i = 0; i < FM; i++)
                    #pragma unroll
                    for (int j = 0; j < FN; j++)
                        wmma::mma_sync(fc[i][j], fa[i], fb[j], fc[i][j]);
            }
        }
    }

    __syncthreads();
    float* sC = (float*)smh_;
    constexpr int LDCS = BN + 4;
    #pragma unroll
    for (int i = 0; i < FM; i++)
        #pragma unroll
        for (int j = 0; j < FN; j++)
            wmma::store_matrix_sync(sC + (wm0 + i * 16) * LDCS + wn0 + j * 16,
                                    fc[i][j], LDCS, wmma::mem_row_major);
    __syncthreads();
    for (int idx = tid; idx < BM * (BN / 4); idx += 256) {
        int r = idx / (BN / 4), c4 = (idx % (BN / 4)) * 4;
        long gm = m0 + r;
        float v0 = sC[r * LDCS + c4 + 0], v1 = sC[r * LDCS + c4 + 1];
        float v2 = sC[r * LDCS + c4 + 2], v3 = sC[r * LDCS + c4 + 3];
        __half2 p0 = __floats2half2_rn(v0, v1);
        __half2 p1 = __floats2half2_rn(v2, v3);
        ((__half2*)(C + gm * INNERi + c4))[0] = p0;
        ((__half2*)(C + gm * INNERi + c4))[1] = p1;
    }
}

// ---------------- fp16 WMMA GEMM, BK=64, 3-stage cp.async ----------------------
__device__ __forceinline__ void cpab(uint32_t s, const void* g)
{ asm volatile("cp.async.cg.shared.global [%0], [%1], 16;\n" :: "r"(s), "l"(g)); }

template<int BM, int BN, bool AC, bool BC, int EPI>
__global__ __launch_bounds__(256)
void ghf(const hf* __restrict__ A, int lda, long aO, long aI,
         const hf* __restrict__ Bm, int ldb, long bO, long bI,
         float* __restrict__ C, hf* __restrict__ Cb,
         int ldc, long cO, long cI,
         const float* __restrict__ bias, long biO,
         const float* __restrict__ res, int ldr, long reO,
         int K, float alpha, int HHd)
{
    constexpr int BK   = 64;
    constexpr int LDAS = AC ? BM + 8 : BK + 8;
    constexpr int AEL  = AC ? BK * LDAS : BM * LDAS;
    constexpr int LDBS = BC ? BK + 8 : BN + 8;
    constexpr int BEL  = BC ? BN * LDBS : BK * LDBS;
    constexpr int SEL  = AEL + BEL;
    constexpr int WRM  = (BN == 128) ? 2 : 4;
    constexpr int WRN  = 8 / WRM;
    constexpr int TM   = BM / WRM, TN = BN / WRN;
    constexpr int FM   = TM / 16, FN = TN / 16;

    extern __shared__ hf smh_[];
    uint32_t sb0;
    asm("{ .reg .u64 t; cvta.to.shared.u64 t, %1; cvt.u32.u64 %0, t; }"
        : "=r"(sb0) : "l"(smh_));

    int z = blockIdx.z, zo = z / HHd, zi = z % HHd;
    A  += (long)zo * aO + (long)zi * aI;
    Bm += (long)zo * bO + (long)zi * bI;
    long m0 = (long)blockIdx.y * BM, n0 = (long)blockIdx.x * BN;
    int tid = threadIdx.x, warp = tid >> 5;
    int wm0 = (warp % WRM) * TM, wn0 = (warp / WRM) * TN;

    auto load_stage = [&](int s, int kt) {
        uint32_t base = sb0 + (uint32_t)(s * SEL * 2);
        int kb = kt * BK;
        if (!AC) {
            constexpr int C8 = BK / 8, TOT = BM * C8;
            #pragma unroll
            for (int t = 0; t < TOT / 256; t++) {
                int idx = t * 256 + tid;
                int r = idx / C8, c = idx % C8;
                cpab(base + (uint32_t)((r * LDAS + c * 8) * 2),
                     A + (m0 + r) * (long)lda + kb + c * 8);
            }
        } else {
            constexpr int C8 = BM / 8, TOT = BK * C8;
            #pragma unroll
            for (int t = 0; t < TOT / 256; t++) {
                int idx = t * 256 + tid;
                int k = idx / C8, mc = idx % C8;
                cpab(base + (uint32_t)((k * LDAS + mc * 8) * 2),
                     A + (long)(kb + k) * lda + m0 + mc * 8);
            }
        }
        if (BC) {
            constexpr int C8 = BK / 8, TOT = BN * C8;
            #pragma unroll
            for (int t = 0; t < TOT / 256; t++) {
                int idx = t * 256 + tid;
                int n = idx / C8, c = idx % C8;
                cpab(base + (uint32_t)((AEL + n * LDBS + c * 8) * 2),
                     Bm + (n0 + n) * (long)ldb + kb + c * 8);
            }
        } else {
            constexpr int C8 = BN / 8, TOT = BK * C8;
            #pragma unroll
            for (int t = 0; t < TOT / 256; t++) {
                int idx = t * 256 + tid;
                int k = idx / C8, c = idx % C8;
                cpab(base + (uint32_t)((AEL + k * LDBS + c * 8) * 2),
                     Bm + (long)(kb + k) * ldb + n0 + c * 8);
            }
        }
        asm volatile("cp.async.commit_group;\n");
    };

    using ALay = typename std::conditional<AC, wmma::col_major, wmma::row_major>::type;
    using BLay = typename std::conditional<BC, wmma::col_major, wmma::row_major>::type;
    wmma::fragment<wmma::accumulator, 16, 16, 16, float> fc[FM][FN];
    #pragma unroll
    for (int i = 0; i < FM; i++)
        #pragma unroll
        for (int j = 0; j < FN; j++)
            wmma::fill_fragment(fc[i][j], 0.f);

    int T = K / BK;
    load_stage(0, 0);
    if (T > 1) load_stage(1, 1);

    for (int kt = 0; kt < T; kt++) {
        if (kt + 1 < T) asm volatile("cp.async.wait_group 1;\n");
        else            asm volatile("cp.async.wait_group 0;\n");
        __syncthreads();
        if (kt + 2 < T) load_stage((kt + 2) % 3, kt + 2);

        const hf* st = smh_ + (kt % 3) * SEL;
        const hf* sA = st;
        const hf* sB = st + AEL;

        #pragma unroll
        for (int kk = 0; kk < BK; kk += 16) {
            wmma::fragment<wmma::matrix_a, 16, 16, 16, hf, ALay> fa[FM];
            wmma::fragment<wmma::matrix_b, 16, 16, 16, hf, BLay> fb[FN];
            #pragma unroll
            for (int i = 0; i < FM; i++) {
                const hf* ap = AC ? (sA + kk * LDAS + wm0 + i * 16)
                                  : (sA + (wm0 + i * 16) * LDAS + kk);
                wmma::load_matrix_sync(fa[i], ap, LDAS);
            }
            #pragma unroll
            for (int j = 0; j < FN; j++) {
                const hf* bp = BC ? (sB + (wn0 + j * 16) * LDBS + kk)
                                  : (sB + kk * LDBS + wn0 + j * 16);
                wmma::load_matrix_sync(fb[j], bp, LDBS);
            }
            #pragma unroll
            for (int i = 0; i < FM; i++)
                #pragma unroll
                for (int j = 0; j < FN; j++)
                    wmma::mma_sync(fc[i][j], fa[i], fb[j], fc[i][j]);
        }
    }

    __syncthreads();
    float* sC = (float*)smh_;
    constexpr int LDCS = BN + 4;
    #pragma unroll
    for (int i = 0; i < FM; i++)
        #pragma unroll
        for (int j = 0; j < FN; j++)
            wmma::store_matrix_sync(sC + (wm0 + i * 16) * LDCS + wn0 + j * 16,
                                    fc[i][j], LDCS, wmma::mem_row_major);
    __syncthreads();
    constexpr int NB4 = BN / 4;
    long cb = (long)zo * cO + (long)zi * cI;
    const float* bz = bias + (long)zo * biO;
    const float* rz = res  + (long)zo * reO;
    for (int idx = tid; idx < BM * NB4; idx += 256) {
        int r = idx / NB4, c4 = (idx % NB4) * 4;
        long gm = m0 + r, gn = n0 + c4;
        float v0 = sC[r * LDCS + c4 + 0], v1 = sC[r * LDCS + c4 + 1];
        float v2 = sC[r * LDCS + c4 + 2], v3 = sC[r * LDCS + c4 + 3];
        if (EPI == 1) {
            __half2 p0 = __floats2half2_rn(v0 * alpha, v1 * alpha);
            __half2 p1 = __floats2half2_rn(v2 * alpha, v3 * alpha);
            ((__half2*)(Cb + cb + gm * ldc + gn))[0] = p0;
            ((__half2*)(Cb + cb + gm * ldc + gn))[1] = p1;
        } else if (EPI == 2) {
            float4 bb = *(const float4*)(bz + gn);
            float4 rr = *(const float4*)(rz + gm * (long)ldr + gn);
            float4 o = { v0 + bb.x + rr.x, v1 + bb.y + rr.y,
                         v2 + bb.z + rr.z, v3 + bb.w + rr.w };
            *(float4*)(C + cb + gm * ldc + gn) = o;
        } else {
            float4 bb = *(const float4*)(bz + gn);
            float t0 = v0 + bb.x, t1 = v1 + bb.y, t2 = v2 + bb.z, t3 = v3 + bb.w;
            t0 = 0.5f * t0 * (1.f + erff(t0 * 0.7071067811865476f));
            t1 = 0.5f * t1 * (1.f + erff(t1 * 0.7071067811865476f));
            t2 = 0.5f * t2 * (1.f + erff(t2 * 0.7071067811865476f));
            t3 = 0.5f * t3 * (1.f + erff(t3 * 0.7071067811865476f));
            __half2 p0 = __floats2half2_rn(t0, t1);
            __half2 p1 = __floats2half2_rn(t2, t3);
            ((__half2*)(Cb + cb + gm * ldc + gn))[0] = p0;
            ((__half2*)(Cb + cb + gm * ldc + gn))[1] = p1;
        }
    }
}

static constexpr size_t gsm(int BM, int BN, bool AC, bool BC)
{
    int BK = 64;
    int LDAS = AC ? BM + 8 : BK + 8;
    int AEL  = AC ? BK * LDAS : BM * LDAS;
    int LDBS = BC ? BK + 8 : BN + 8;
    int BEL  = BC ? BN * LDBS : BK * LDBS;
    size_t pipe = 3u * 2u * (size_t)(AEL + BEL);
    size_t epi  = 4u * (size_t)BM * (BN + 4);
    return pipe > epi ? pipe : epi;
}

#define LGH(BM, BN, AC, BC, EPI, grid, ...)                                      \
    do {                                                                         \
        auto kfn = ghf<BM, BN, AC, BC, EPI>;                                     \
        size_t smb = gsm(BM, BN, AC, BC);                                        \
        cudaFuncSetAttribute(kfn, cudaFuncAttributeMaxDynamicSharedMemorySize, (int)smb); \
        kfn<<<grid, 256, smb>>>(__VA_ARGS__);                                    \
    } while (0)

// ---------------- host ----------------------------------------------------------
extern "C" void kernel_launch(void* const* d_in, const int* in_sizes, int n_in,
                              void* d_out, int out_size)
{
    (void)in_sizes; (void)n_in; (void)out_size;
    const float* x      = (const float*)d_in[0];
    const float* ctx    = (const float*)d_in[1];
    const void*  mask   = d_in[2];
    const void*  cmask  = d_in[3];
    const float* ln_x_g = (const float*)d_in[4];
    const float* ln_x_b = (const float*)d_in[5];
    const float* ln_c_g = (const float*)d_in[6];
    const float* ln_c_b = (const float*)d_in[7];
    const float* W_qk   = (const float*)d_in[8];
    const float* W_v    = (const float*)d_in[9];
    const float* Wc_qk  = (const float*)d_in[10];
    const float* Wc_v   = (const float*)d_in[11];
    const float* W_out  = (const float*)d_in[12];
    const float* b_out  = (const float*)d_in[13];
    const float* Wc_out = (const float*)d_in[14];
    const float* bc_out = (const float*)d_in[15];
    const float* ff_g   = (const float*)d_in[16];
    const float* ff_b   = (const float*)d_in[17];
    const float* ff_w1  = (const float*)d_in[18];
    const float* ff_b1  = (const float*)d_in[19];
    const float* ff_w2  = (const float*)d_in[20];
    const float* ff_b2  = (const float*)d_in[21];
    const float* cff_g  = (const float*)d_in[22];
    const float* cff_b  = (const float*)d_in[23];
    const float* cff_w1 = (const float*)d_in[24];
    const float* cff_b1 = (const float*)d_in[25];
    const float* cff_w2 = (const float*)d_in[26];
    const float* cff_b2 = (const float*)d_in[27];
    float* outp = (float*)d_out;

    float *x1c, *resin, *bo, *b1, *b2;
    hf *simb, *attn, *cattn, *qkv, *oc, *xc, *hb, *wp, *wo, *f1, *f2;
    cudaGetSymbolAddress((void**)&x1c,   g_x1c);
    cudaGetSymbolAddress((void**)&resin, g_resin);
    cudaGetSymbolAddress((void**)&bo,    g_bo);
    cudaGetSymbolAddress((void**)&b1,    g_b1);
    cudaGetSymbolAddress((void**)&b2,    g_b2);
    cudaGetSymbolAddress((void**)&simb,  g_simb);
    cudaGetSymbolAddress((void**)&attn,  g_attn);
    cudaGetSymbolAddress((void**)&cattn, g_cattn);
    cudaGetSymbolAddress((void**)&qkv,   g_qkv);
    cudaGetSymbolAddress((void**)&oc,    g_oc);
    cudaGetSymbolAddress((void**)&xc,    g_xc);
    cudaGetSymbolAddress((void**)&hb,    g_hb);
    cudaGetSymbolAddress((void**)&wp,    g_wp);
    cudaGetSymbolAddress((void**)&wo,    g_wo);
    cudaGetSymbolAddress((void**)&f1,    g_f1);
    cudaGetSymbolAddress((void**)&f2,    g_f2);

    const float SCALE = 0.125f;
    const float* nf = nullptr;
    hf* nh = nullptr;

    // 0) mask dtype; merged weight convert; concat copies
    detect_mask_mode<<<1, 256>>>((const float*)mask, (Bb * Nn) / 4);
    convall<<<dim3(512, 10), 256>>>(
        (const float4*)W_qk,  (const float4*)W_v,   (const float4*)Wc_qk,
        (const float4*)Wc_v,  (const float4*)W_out, (const float4*)Wc_out,
        (const float4*)ff_w1, (const float4*)cff_w1,
        (const float4*)ff_w2, (const float4*)cff_w2,
        (__half2*)(wp + 0L * DW), (__half2*)(wp + 1L * DW),
        (__half2*)(wp + 2L * DW), (__half2*)(wp + 3L * DW),
        (__half2*)(wo + 0L * DW), (__half2*)(wo + 1L * DW),
        (__half2*)(f1 + 0L * DF), (__half2*)(f1 + 1L * DF),
        (__half2*)(f2 + 0L * DF), (__half2*)(f2 + 1L * DF));
    cudaMemcpyAsync(bo,       b_out,   Dd * 4,   cudaMemcpyDeviceToDevice, 0);
    cudaMemcpyAsync(bo + Dd,  bc_out,  Dd * 4,   cudaMemcpyDeviceToDevice, 0);
    cudaMemcpyAsync(b1,        ff_b1,  FFDf * 4, cudaMemcpyDeviceToDevice, 0);
    cudaMemcpyAsync(b1 + FFDf, cff_b1, FFDf * 4, cudaMemcpyDeviceToDevice, 0);
    cudaMemcpyAsync(b2,       ff_b2,   Dd * 4,   cudaMemcpyDeviceToDevice, 0);
    cudaMemcpyAsync(b2 + Dd,  cff_b2,  Dd * 4,   cudaMemcpyDeviceToDevice, 0);
    cudaMemcpyAsync(resin,        x,   (size_t)BND * 4, cudaMemcpyDeviceToDevice, 0);
    cudaMemcpyAsync(resin + BND,  ctx, (size_t)BND * 4, cudaMemcpyDeviceToDevice, 0);

    // 1) pre-norm both sides -> xc
    ln2<<<2 * Bb * Nn, 256>>>(x, ctx, Bb * Nn, ln_x_g, ln_x_b, ln_c_g, ln_c_b, xc, Dd);

    // 2) all 4 projections in ONE launch
    LGH(128, 128, false, false, 1, dim3(INNERi / 128, Bb * Nn / 128, 4),
        xc, Dd, BND, 0,
        wp, INNERi, 2L * DW, DW,
        (float*)nullptr, qkv, INNERi, 2L * BNI, BNI,
        nf, 0, nf, 0, 0, Dd, 1.f, 2);

    // 3) sim = qk @ cqk^T * SCALE -> fp16
    LGH(128, 128, false, true, 1, dim3(MM_ / 128, Nn / 128, Bb * Hh),
        qkv, INNERi, (long)Nn * INNERi, DHd,
        qkv + 2L * BNI, INNERi, (long)MM_ * INNERi, DHd,
        (float*)nullptr, simb, MM_, (long)Hh * Nn * MM_, (long)Nn * MM_,
        nf, 0, nf, 0, 0, DHd, SCALE, Hh);

    // 4) fused dual softmax (one launch; col blocks overlap row tail)
    softmax_both<<<ROWBLK + COLBLK, 256>>>(simb, attn, cattn, mask, cmask);

    // 5) fused PV (one launch, 32 z-slices)
    {
        size_t smb = 3u * 2u * (size_t)((128 * 72) + (64 * 72));
        size_t epi = 4u * 128 * 68;
        if (epi > smb) smb = epi;
        cudaFuncSetAttribute(pv2, cudaFuncAttributeMaxDynamicSharedMemorySize, (int)smb);
        pv2<<<dim3(1, Nn / 128, 32), 256, smb>>>(attn, cattn, qkv + 1L * BNI,
                                                 qkv + 3L * BNI, oc);
    }

    // 6) out-proj + residual, both sides -> x1 | c1
    LGH(128, 128, false, false, 2, dim3(Dd / 128, Bb * Nn / 128, 2),
        oc, INNERi, BNI, 0,
        wo, Dd, DW, 0,
        x1c, nh, Dd, BND, 0,
        bo, Dd, resin, Dd, BND, INNERi, 1.f, 1);

    // 7) FFN LN both sides -> xc
    ln2<<<2 * Bb * Nn, 256>>>(x1c, x1c + BND, Bb * Nn, ff_g, ff_b, cff_g, cff_b, xc, Dd);

    // 8) FFN1 both sides (GELU -> fp16)
    LGH(128, 128, false, false, 3, dim3(FFDf / 128, Bb * Nn / 128, 2),
        xc, Dd, BND, 0,
        f1, FFDf, DF, 0,
        (float*)nullptr, hb, FFDf, (long)BNF, 0,
        b1, FFDf, nf, 0, 0, Dd, 1.f, 1);

    // 9) FFN2 both sides -> d_out directly
    LGH(128, 128, false, false, 2, dim3(Dd / 128, Bb * Nn / 128, 2),
        hb, FFDf, (long)BNF, 0,
        f2, Dd, DF, 0,
        outp, nh, Dd, BND, 0,
        b2, Dd, x1c, Dd, BND, FFDf, 1.f, 1);
}

// round 17
// speedup vs baseline: 1.4070x; 1.4070x over previous
#include <cuda_runtime.h>
#include <cuda_fp16.h>
#include <mma.h>
#include <math.h>
#include <cstdint>

using namespace nvcuda;
typedef __half hf;

#define Bb 2
#define Nn 2048
#define MM_ 2048
#define Dd 1024
#define Hh 8
#define DHd 64
#define INNERi 512
#define FFDf 4096

#define BND  (Bb*Nn*Dd)
#define BNI  (Bb*Nn*INNERi)
#define BNF  (Bb*Nn*FFDf)
#define DW   (Dd*INNERi)
#define DF   ((long)Dd*FFDf)

// ---------------- scratch ----------------------------------------------------
__device__ __align__(256) float g_x1c [2*BND];
__device__ __align__(256) float g_resin[2*BND];
__device__ __align__(256) float g_bo[2*Dd];
__device__ __align__(256) float g_b1[2*FFDf];
__device__ __align__(256) float g_b2[2*Dd];
__device__ __align__(256) hf g_simb [Bb*Hh*Nn*MM_];
__device__ __align__(256) hf g_attn [Bb*Hh*Nn*MM_];
__device__ __align__(256) hf g_cattn[Bb*Hh*Nn*MM_];
__device__ __align__(256) hf g_qkv[4*BNI];
__device__ __align__(256) hf g_oc [2*BNI];
__device__ __align__(256) hf g_xc [2*BND];
__device__ __align__(256) hf g_hb [2*BNF];
__device__ __align__(256) hf g_wp [4*DW];
__device__ __align__(256) hf g_wo [2*DW];
__device__ __align__(256) hf g_f1 [2*DF];
__device__ __align__(256) hf g_f2 [2*DF];
__device__ int g_mask_mode;

// ---------------- merged f32 -> fp16 weight convert (10 segments) --------------
__global__ __launch_bounds__(256)
void convall(const float4* s0, const float4* s1, const float4* s2, const float4* s3,
             const float4* s4, const float4* s5, const float4* s6, const float4* s7,
             const float4* s8, const float4* s9,
             __half2* d0, __half2* d1, __half2* d2, __half2* d3, __half2* d4,
             __half2* d5, __half2* d6, __half2* d7, __half2* d8, __half2* d9)
{
    int seg = blockIdx.y;
    const float4* in; __half2* out; int n4;
    switch (seg) {
        case 0: in = s0; out = d0; n4 = DW / 4; break;
        case 1: in = s1; out = d1; n4 = DW / 4; break;
        case 2: in = s2; out = d2; n4 = DW / 4; break;
        case 3: in = s3; out = d3; n4 = DW / 4; break;
        case 4: in = s4; out = d4; n4 = DW / 4; break;
        case 5: in = s5; out = d5; n4 = DW / 4; break;
        case 6: in = s6; out = d6; n4 = (int)(DF / 4); break;
        case 7: in = s7; out = d7; n4 = (int)(DF / 4); break;
        case 8: in = s8; out = d8; n4 = (int)(DF / 4); break;
        default: in = s9; out = d9; n4 = (int)(DF / 4); break;
    }
    for (int i = blockIdx.x * 256 + threadIdx.x; i < n4; i += gridDim.x * 256) {
        float4 v = in[i];
        out[2 * i]     = __floats2half2_rn(v.x, v.y);
        out[2 * i + 1] = __floats2half2_rn(v.z, v.w);
    }
}

// ---------------- mask detection ---------------------------------------------
__global__ void detect_mask_mode(const float* __restrict__ fp, int n4)
{
    __shared__ int okf_s, oki_s;
    if (threadIdx.x == 0) { okf_s = 1; oki_s = 1; }
    __syncthreads();
    const int* ip = (const int*)fp;
    bool okf = true, oki = true;
    for (int i = threadIdx.x; i < n4; i += 256) {
        float fv = fp[i]; okf = okf && (fv == 0.f || fv == 1.f);
        int   iv = ip[i]; oki = oki && (iv == 0 || iv == 1);
    }
    if (!okf) atomicAnd(&okf_s, 0);
    if (!oki) atomicAnd(&oki_s, 0);
    __syncthreads();
    if (threadIdx.x == 0) g_mask_mode = okf_s ? 2 : (oki_s ? 1 : 0);
}
__device__ __forceinline__ bool mask_at(const void* m, int i, int mode)
{
    if (mode == 1) return ((const int*)m)[i] != 0;
    if (mode == 2) return ((const float*)m)[i] != 0.f;
    return ((const unsigned char*)m)[i] != 0;
}

// ---------------- dual-side LayerNorm -> fp16 ----------------------------------
__global__ __launch_bounds__(256)
void ln2(const float* __restrict__ inA, const float* __restrict__ inB, int RA,
         const float* __restrict__ gA, const float* __restrict__ bA,
         const float* __restrict__ gB, const float* __restrict__ bB,
         hf* __restrict__ oh, int cols)
{
    __shared__ float r1[256], r2[256];
    long row = blockIdx.x;
    bool sec = row >= RA;
    const float* p = sec ? inB + (row - RA) * cols : inA + row * cols;
    const float* g = sec ? gB : gA;
    const float* b = sec ? bB : bA;
    hf* ph = oh + row * cols;
    int tid = threadIdx.x;
    float s = 0.f, s2 = 0.f;
    for (int c = tid; c < cols; c += 256) { float v = p[c]; s += v; s2 += v * v; }
    r1[tid] = s; r2[tid] = s2; __syncthreads();
    for (int st = 128; st > 0; st >>= 1) {
        if (tid < st) { r1[tid] += r1[tid + st]; r2[tid] += r2[tid + st]; }
        __syncthreads();
    }
    float mu  = r1[0] / cols;
    float var = r2[0] / cols - mu * mu;
    float inv = rsqrtf(var + 1e-5f);
    for (int c = tid; c < cols; c += 256)
        ph[c] = __float2half((p[c] - mu) * inv * g[c] + b[c]);
}

// ---------------- dual softmax --------------------------------------------------
__global__ __launch_bounds__(256)
void softmax_row(const hf* __restrict__ sim, hf* __restrict__ attn,
                 const void* __restrict__ mask, const void* __restrict__ cmask)
{
    __shared__ float buf[MM_];
    __shared__ float red[256];
    int mode = g_mask_mode;
    long row = blockIdx.x;
    int i = (int)(row % Nn), bh = (int)(row / Nn), b = bh / Hh;
    const __half2* src2 = (const __half2*)(sim + row * (long)MM_);
    __half2*       dst2 = (__half2*)(attn + row * (long)MM_);
    int tid = threadIdx.x;
    bool mi = mask_at(mask, b * Nn + i, mode);
    float lmax = -3.402823466e38f;
    for (int j2 = tid; j2 < MM_ / 2; j2 += 256) {
        __half2 hv = src2[j2];
        int j = j2 * 2;
        bool mj0 = mask_at(cmask, b * MM_ + j, mode);
        bool mj1 = mask_at(cmask, b * MM_ + j + 1, mode);
        float v0 = (mi && mj0) ? __half2float(hv.x) : -3.402823466e38f;
        float v1 = (mi && mj1) ? __half2float(hv.y) : -3.402823466e38f;
        buf[j] = v0; buf[j + 1] = v1;
        lmax = fmaxf(lmax, fmaxf(v0, v1));
    }
    red[tid] = lmax; __syncthreads();
    for (int s = 128; s > 0; s >>= 1) {
        if (tid < s) red[tid] = fmaxf(red[tid], red[tid + s]);
        __syncthreads();
    }
    float rmax = red[0]; __syncthreads();
    float lsum = 0.f;
    for (int j = tid; j < MM_; j += 256) {
        float e = __expf(buf[j] - rmax);
        buf[j] = e; lsum += e;
    }
    red[tid] = lsum; __syncthreads();
    for (int s = 128; s > 0; s >>= 1) {
        if (tid < s) red[tid] += red[tid + s];
        __syncthreads();
    }
    float inv = 1.f / red[0];
    for (int j2 = tid; j2 < MM_ / 2; j2 += 256)
        dst2[j2] = __floats2half2_rn(buf[j2 * 2] * inv, buf[j2 * 2 + 1] * inv);
}

// 32 cols x 8 row-groups (proven shape: max TLP on the serial exp chain).
__global__ __launch_bounds__(256)
void softmax_col(const hf* __restrict__ sim, hf* __restrict__ cattn,
                 const void* __restrict__ mask, const void* __restrict__ cmask)
{
    __shared__ float sm[8][32], ss[8][32];
    int mode = g_mask_mode;
    int z = blockIdx.y, b = z / Hh;
    int c = threadIdx.x & 31, g = threadIdx.x >> 5;
    int j = blockIdx.x * 32 + c;
    const hf* base = sim   + (long)z * Nn * MM_;
    hf*       outb = cattn + (long)z * Nn * MM_;
    bool mj = mask_at(cmask, b * MM_ + j, mode);
    float m = -3.402823466e38f, s = 0.f;
    for (int i = g; i < Nn; i += 8) {
        bool mi = mask_at(mask, b * Nn + i, mode);
        float vv = (mj && mi) ? __half2float(base[(long)i * MM_ + j]) : -3.402823466e38f;
        if (vv > m) { s = s * __expf(m - vv) + 1.f; m = vv; }
        else        { s += __expf(vv - m); }
    }
    sm[g][c] = m; ss[g][c] = s; __syncthreads();
    if (g == 0) {
        float Ml = sm[0][c], Sl = ss[0][c];
        #pragma unroll
        for (int t = 1; t < 8; t++) {
            float mt = sm[t][c], st = ss[t][c];
            float nm = fmaxf(Ml, mt);
            Sl = Sl * __expf(Ml - nm) + st * __expf(mt - nm);
            Ml = nm;
        }
        sm[0][c] = Ml; ss[0][c] = 1.f / Sl;
    }
    __syncthreads();
    float Mg = sm[0][c], inv = ss[0][c];
    for (int i = g; i < Nn; i += 8) {
        bool mi = mask_at(mask, b * Nn + i, mode);
        float vv = (mj && mi) ? __half2float(base[(long)i * MM_ + j]) : -3.402823466e38f;
        outb[(long)i * MM_ + j] = __float2half(__expf(vv - Mg) * inv);
    }
}

// ---------------- fp16 WMMA GEMM, BK=64, 3-stage cp.async ----------------------
__device__ __forceinline__ void cpab(uint32_t s, const void* g)
{ asm volatile("cp.async.cg.shared.global [%0], [%1], 16;\n" :: "r"(s), "l"(g)); }

template<int BM, int BN, bool AC, bool BC, int EPI>
__global__ __launch_bounds__(256)
void ghf(const hf* __restrict__ A, int lda, long aO, long aI,
         const hf* __restrict__ Bm, int ldb, long bO, long bI,
         float* __restrict__ C, hf* __restrict__ Cb,
         int ldc, long cO, long cI,
         const float* __restrict__ bias, long biO,
         const float* __restrict__ res, int ldr, long reO,
         int K, float alpha, int HHd)
{
    constexpr int BK   = 64;
    constexpr int LDAS = AC ? BM + 8 : BK + 8;
    constexpr int AEL  = AC ? BK * LDAS : BM * LDAS;
    constexpr int LDBS = BC ? BK + 8 : BN + 8;
    constexpr int BEL  = BC ? BN * LDBS : BK * LDBS;
    constexpr int SEL  = AEL + BEL;
    constexpr int WRM  = (BN == 128) ? 2 : 4;
    constexpr int WRN  = 8 / WRM;
    constexpr int TM   = BM / WRM, TN = BN / WRN;
    constexpr int FM   = TM / 16, FN = TN / 16;

    extern __shared__ hf smh_[];
    uint32_t sb0;
    asm("{ .reg .u64 t; cvta.to.shared.u64 t, %1; cvt.u32.u64 %0, t; }"
        : "=r"(sb0) : "l"(smh_));

    int z = blockIdx.z, zo = z / HHd, zi = z % HHd;
    A  += (long)zo * aO + (long)zi * aI;
    Bm += (long)zo * bO + (long)zi * bI;
    long m0 = (long)blockIdx.y * BM, n0 = (long)blockIdx.x * BN;
    int tid = threadIdx.x, warp = tid >> 5;
    int wm0 = (warp % WRM) * TM, wn0 = (warp / WRM) * TN;

    auto load_stage = [&](int s, int kt) {
        uint32_t base = sb0 + (uint32_t)(s * SEL * 2);
        int kb = kt * BK;
        if (!AC) {
            constexpr int C8 = BK / 8, TOT = BM * C8;
            #pragma unroll
            for (int t = 0; t < TOT / 256; t++) {
                int idx = t * 256 + tid;
                int r = idx / C8, c = idx % C8;
                cpab(base + (uint32_t)((r * LDAS + c * 8) * 2),
                     A + (m0 + r) * (long)lda + kb + c * 8);
            }
        } else {
            constexpr int C8 = BM / 8, TOT = BK * C8;
            #pragma unroll
            for (int t = 0; t < TOT / 256; t++) {
                int idx = t * 256 + tid;
                int k = idx / C8, mc = idx % C8;
                cpab(base + (uint32_t)((k * LDAS + mc * 8) * 2),
                     A + (long)(kb + k) * lda + m0 + mc * 8);
            }
        }
        if (BC) {
            constexpr int C8 = BK / 8, TOT = BN * C8;
            #pragma unroll
            for (int t = 0; t < TOT / 256; t++) {
                int idx = t * 256 + tid;
                int n = idx / C8, c = idx % C8;
                cpab(base + (uint32_t)((AEL + n * LDBS + c * 8) * 2),
                     Bm + (n0 + n) * (long)ldb + kb + c * 8);
            }
        } else {
            constexpr int C8 = BN / 8, TOT = BK * C8;
            #pragma unroll
            for (int t = 0; t < TOT / 256; t++) {
                int idx = t * 256 + tid;
                int k = idx / C8, c = idx % C8;
                cpab(base + (uint32_t)((AEL + k * LDBS + c * 8) * 2),
                     Bm + (long)(kb + k) * ldb + n0 + c * 8);
            }
        }
        asm volatile("cp.async.commit_group;\n");
    };

    using ALay = typename std::conditional<AC, wmma::col_major, wmma::row_major>::type;
    using BLay = typename std::conditional<BC, wmma::col_major, wmma::row_major>::type;
    wmma::fragment<wmma::accumulator, 16, 16, 16, float> fc[FM][FN];
    #pragma unroll
    for (int i = 0; i < FM; i++)
        #pragma unroll
        for (int j = 0; j < FN; j++)
            wmma::fill_fragment(fc[i][j], 0.f);

    int T = K / BK;
    load_stage(0, 0);
    if (T > 1) load_stage(1, 1);

    for (int kt = 0; kt < T; kt++) {
        if (kt + 1 < T) asm volatile("cp.async.wait_group 1;\n");
        else            asm volatile("cp.async.wait_group 0;\n");
        __syncthreads();
        if (kt + 2 < T) load_stage((kt + 2) % 3, kt + 2);

        const hf* st = smh_ + (kt % 3) * SEL;
        const hf* sA = st;
        const hf* sB = st + AEL;

        #pragma unroll
        for (int kk = 0; kk < BK; kk += 16) {
            wmma::fragment<wmma::matrix_a, 16, 16, 16, hf, ALay> fa[FM];
            wmma::fragment<wmma::matrix_b, 16, 16, 16, hf, BLay> fb[FN];
            #pragma unroll
            for (int i = 0; i < FM; i++) {
                const hf* ap = AC ? (sA + kk * LDAS + wm0 + i * 16)
                                  : (sA + (wm0 + i * 16) * LDAS + kk);
                wmma::load_matrix_sync(fa[i], ap, LDAS);
            }
            #pragma unroll
            for (int j = 0; j < FN; j++) {
                const hf* bp = BC ? (sB + (wn0 + j * 16) * LDBS + kk)
                                  : (sB + kk * LDBS + wn0 + j * 16);
                wmma::load_matrix_sync(fb[j], bp, LDBS);
            }
            #pragma unroll
            for (int i = 0; i < FM; i++)
                #pragma unroll
                for (int j = 0; j < FN; j++)
                    wmma::mma_sync(fc[i][j], fa[i], fb[j], fc[i][j]);
        }
    }

    __syncthreads();
    float* sC = (float*)smh_;
    constexpr int LDCS = BN + 4;
    #pragma unroll
    for (int i = 0; i < FM; i++)
        #pragma unroll
        for (int j = 0; j < FN; j++)
            wmma::store_matrix_sync(sC + (wm0 + i * 16) * LDCS + wn0 + j * 16,
                                    fc[i][j], LDCS, wmma::mem_row_major);
    __syncthreads();
    constexpr int NB4 = BN / 4;
    long cb = (long)zo * cO + (long)zi * cI;
    const float* bz = bias + (long)zo * biO;
    const float* rz = res  + (long)zo * reO;
    for (int idx = tid; idx < BM * NB4; idx += 256) {
        int r = idx / NB4, c4 = (idx % NB4) * 4;
        long gm = m0 + r, gn = n0 + c4;
        float v0 = sC[r * LDCS + c4 + 0], v1 = sC[r * LDCS + c4 + 1];
        float v2 = sC[r * LDCS + c4 + 2], v3 = sC[r * LDCS + c4 + 3];
        if (EPI == 1) {
            __half2 p0 = __floats2half2_rn(v0 * alpha, v1 * alpha);
            __half2 p1 = __floats2half2_rn(v2 * alpha, v3 * alpha);
            ((__half2*)(Cb + cb + gm * ldc + gn))[0] = p0;
            ((__half2*)(Cb + cb + gm * ldc + gn))[1] = p1;
        } else if (EPI == 2) {
            float4 bb = *(const float4*)(bz + gn);
            float4 rr = *(const float4*)(rz + gm * (long)ldr + gn);
            float4 o = { v0 + bb.x + rr.x, v1 + bb.y + rr.y,
                         v2 + bb.z + rr.z, v3 + bb.w + rr.w };
            *(float4*)(C + cb + gm * ldc + gn) = o;
        } else {
            float4 bb = *(const float4*)(bz + gn);
            float t0 = v0 + bb.x, t1 = v1 + bb.y, t2 = v2 + bb.z, t3 = v3 + bb.w;
            t0 = 0.5f * t0 * (1.f + erff(t0 * 0.7071067811865476f));
            t1 = 0.5f * t1 * (1.f + erff(t1 * 0.7071067811865476f));
            t2 = 0.5f * t2 * (1.f + erff(t2 * 0.7071067811865476f));
            t3 = 0.5f * t3 * (1.f + erff(t3 * 0.7071067811865476f));
            __half2 p0 = __floats2half2_rn(t0, t1);
            __half2 p1 = __floats2half2_rn(t2, t3);
            ((__half2*)(Cb + cb + gm * ldc + gn))[0] = p0;
            ((__half2*)(Cb + cb + gm * ldc + gn))[1] = p1;
        }
    }
}

static constexpr size_t gsm(int BM, int BN, bool AC, bool BC)
{
    int BK = 64;
    int LDAS = AC ? BM + 8 : BK + 8;
    int AEL  = AC ? BK * LDAS : BM * LDAS;
    int LDBS = BC ? BK + 8 : BN + 8;
    int BEL  = BC ? BN * LDBS : BK * LDBS;
    size_t pipe = 3u * 2u * (size_t)(AEL + BEL);
    size_t epi  = 4u * (size_t)BM * (BN + 4);
    return pipe > epi ? pipe : epi;
}

#define LGH(BM, BN, AC, BC, EPI, grid, ...)                                      \
    do {                                                                         \
        auto kfn = ghf<BM, BN, AC, BC, EPI>;                                     \
        size_t smb = gsm(BM, BN, AC, BC);                                        \
        cudaFuncSetAttribute(kfn, cudaFuncAttributeMaxDynamicSharedMemorySize, (int)smb); \
        kfn<<<grid, 256, smb>>>(__VA_ARGS__);                                    \
    } while (0)

// ---------------- host ----------------------------------------------------------
extern "C" void kernel_launch(void* const* d_in, const int* in_sizes, int n_in,
                              void* d_out, int out_size)
{
    (void)in_sizes; (void)n_in; (void)out_size;
    const float* x      = (const float*)d_in[0];
    const float* ctx    = (const float*)d_in[1];
    const void*  mask   = d_in[2];
    const void*  cmask  = d_in[3];
    const float* ln_x_g = (const float*)d_in[4];
    const float* ln_x_b = (const float*)d_in[5];
    const float* ln_c_g = (const float*)d_in[6];
    const float* ln_c_b = (const float*)d_in[7];
    const float* W_qk   = (const float*)d_in[8];
    const float* W_v    = (const float*)d_in[9];
    const float* Wc_qk  = (const float*)d_in[10];
    const float* Wc_v   = (const float*)d_in[11];
    const float* W_out  = (const float*)d_in[12];
    const float* b_out  = (const float*)d_in[13];
    const float* Wc_out = (const float*)d_in[14];
    const float* bc_out = (const float*)d_in[15];
    const float* ff_g   = (const float*)d_in[16];
    const float* ff_b   = (const float*)d_in[17];
    const float* ff_w1  = (const float*)d_in[18];
    const float* ff_b1  = (const float*)d_in[19];
    const float* ff_w2  = (const float*)d_in[20];
    const float* ff_b2  = (const float*)d_in[21];
    const float* cff_g  = (const float*)d_in[22];
    const float* cff_b  = (const float*)d_in[23];
    const float* cff_w1 = (const float*)d_in[24];
    const float* cff_b1 = (const float*)d_in[25];
    const float* cff_w2 = (const float*)d_in[26];
    const float* cff_b2 = (const float*)d_in[27];
    float* outp = (float*)d_out;

    float *x1c, *resin, *bo, *b1, *b2;
    hf *simb, *attn, *cattn, *qkv, *oc, *xc, *hb, *wp, *wo, *f1, *f2;
    cudaGetSymbolAddress((void**)&x1c,   g_x1c);
    cudaGetSymbolAddress((void**)&resin, g_resin);
    cudaGetSymbolAddress((void**)&bo,    g_bo);
    cudaGetSymbolAddress((void**)&b1,    g_b1);
    cudaGetSymbolAddress((void**)&b2,    g_b2);
    cudaGetSymbolAddress((void**)&simb,  g_simb);
    cudaGetSymbolAddress((void**)&attn,  g_attn);
    cudaGetSymbolAddress((void**)&cattn, g_cattn);
    cudaGetSymbolAddress((void**)&qkv,   g_qkv);
    cudaGetSymbolAddress((void**)&oc,    g_oc);
    cudaGetSymbolAddress((void**)&xc,    g_xc);
    cudaGetSymbolAddress((void**)&hb,    g_hb);
    cudaGetSymbolAddress((void**)&wp,    g_wp);
    cudaGetSymbolAddress((void**)&wo,    g_wo);
    cudaGetSymbolAddress((void**)&f1,    g_f1);
    cudaGetSymbolAddress((void**)&f2,    g_f2);

    const float SCALE = 0.125f;
    const float* nf = nullptr;
    hf* nh = nullptr;

    // 0) mask dtype; merged weight convert; concat copies
    detect_mask_mode<<<1, 256>>>((const float*)mask, (Bb * Nn) / 4);
    convall<<<dim3(512, 10), 256>>>(
        (const float4*)W_qk,  (const float4*)W_v,   (const float4*)Wc_qk,
        (const float4*)Wc_v,  (const float4*)W_out, (const float4*)Wc_out,
        (const float4*)ff_w1, (const float4*)cff_w1,
        (const float4*)ff_w2, (const float4*)cff_w2,
        (__half2*)(wp + 0L * DW), (__half2*)(wp + 1L * DW),
        (__half2*)(wp + 2L * DW), (__half2*)(wp + 3L * DW),
        (__half2*)(wo + 0L * DW), (__half2*)(wo + 1L * DW),
        (__half2*)(f1 + 0L * DF), (__half2*)(f1 + 1L * DF),
        (__half2*)(f2 + 0L * DF), (__half2*)(f2 + 1L * DF));
    cudaMemcpyAsync(bo,       b_out,   Dd * 4,   cudaMemcpyDeviceToDevice, 0);
    cudaMemcpyAsync(bo + Dd,  bc_out,  Dd * 4,   cudaMemcpyDeviceToDevice, 0);
    cudaMemcpyAsync(b1,        ff_b1,  FFDf * 4, cudaMemcpyDeviceToDevice, 0);
    cudaMemcpyAsync(b1 + FFDf, cff_b1, FFDf * 4, cudaMemcpyDeviceToDevice, 0);
    cudaMemcpyAsync(b2,       ff_b2,   Dd * 4,   cudaMemcpyDeviceToDevice, 0);
    cudaMemcpyAsync(b2 + Dd,  cff_b2,  Dd * 4,   cudaMemcpyDeviceToDevice, 0);
    cudaMemcpyAsync(resin,        x,   (size_t)BND * 4, cudaMemcpyDeviceToDevice, 0);
    cudaMemcpyAsync(resin + BND,  ctx, (size_t)BND * 4, cudaMemcpyDeviceToDevice, 0);

    // 1) pre-norm both sides -> xc
    ln2<<<2 * Bb * Nn, 256>>>(x, ctx, Bb * Nn, ln_x_g, ln_x_b, ln_c_g, ln_c_b, xc, Dd);

    // 2) all 4 projections in ONE launch
    LGH(128, 128, false, false, 1, dim3(INNERi / 128, Bb * Nn / 128, 4),
        xc, Dd, BND, 0,
        wp, INNERi, 2L * DW, DW,
        (float*)nullptr, qkv, INNERi, 2L * BNI, BNI,
        nf, 0, nf, 0, 0, Dd, 1.f, 2);

    // 3) sim = qk @ cqk^T * SCALE -> fp16
    LGH(128, 128, false, true, 1, dim3(MM_ / 128, Nn / 128, Bb * Hh),
        qkv, INNERi, (long)Nn * INNERi, DHd,
        qkv + 2L * BNI, INNERi, (long)MM_ * INNERi, DHd,
        (float*)nullptr, simb, MM_, (long)Hh * Nn * MM_, (long)Nn * MM_,
        nf, 0, nf, 0, 0, DHd, SCALE, Hh);

    // 4) dual softmax (separate launches — R15-proven)
    softmax_row<<<Bb * Hh * Nn, 256>>>(simb, attn, mask, cmask);
    softmax_col<<<dim3(MM_ / 32, Bb * Hh), 256>>>(simb, cattn, mask, cmask);

    // 5) PV (two launches — R15-proven)
    LGH(128, 64, false, false, 1, dim3(1, Nn / 128, Bb * Hh),
        attn, MM_, (long)Hh * Nn * MM_, (long)Nn * MM_,
        qkv + 3L * BNI, INNERi, (long)MM_ * INNERi, DHd,
        (float*)nullptr, oc, INNERi, (long)Nn * INNERi, DHd,
        nf, 0, nf, 0, 0, MM_, 1.f, Hh);
    LGH(128, 64, true, false, 1, dim3(1, MM_ / 128, Bb * Hh),
        cattn, MM_, (long)Hh * Nn * MM_, (long)Nn * MM_,
        qkv + 1L * BNI, INNERi, (long)Nn * INNERi, DHd,
        (float*)nullptr, oc + BNI, INNERi, (long)MM_ * INNERi, DHd,
        nf, 0, nf, 0, 0, Nn, 1.f, Hh);

    // 6) out-proj + residual, both sides -> x1 | c1
    LGH(128, 128, false, false, 2, dim3(Dd / 128, Bb * Nn / 128, 2),
        oc, INNERi, BNI, 0,
        wo, Dd, DW, 0,
        x1c, nh, Dd, BND, 0,
        bo, Dd, resin, Dd, BND, INNERi, 1.f, 1);

    // 7) FFN LN both sides -> xc
    ln2<<<2 * Bb * Nn, 256>>>(x1c, x1c + BND, Bb * Nn, ff_g, ff_b, cff_g, cff_b, xc, Dd);

    // 8) FFN1 both sides (GELU -> fp16)
    LGH(128, 128, false, false, 3, dim3(FFDf / 128, Bb * Nn / 128, 2),
        xc, Dd, BND, 0,
        f1, FFDf, DF, 0,
        (float*)nullptr, hb, FFDf, (long)BNF, 0,
        b1, FFDf, nf, 0, 0, Dd, 1.f, 1);

    // 9) FFN2 both sides -> d_out directly
    LGH(128, 128, false, false, 2, dim3(Dd / 128, Bb * Nn / 128, 2),
        hb, FFDf, (long)BNF, 0,
        f2, Dd, DF, 0,
        outp, nh, Dd, BND, 0,
        b2, Dd, x1c, Dd, BND, FFDf, 1.f, 1);
}